// round 8
// baseline (speedup 1.0000x reference)
#include <cuda_runtime.h>
#include <cuda_fp16.h>
#include <math.h>

#define NB 16
#define H 512
#define W 512
#define KR 15
#define KKINV (1.0f/961.0f)
#define MUF 5.0f
#define RPB 16                        // rows per block in vert kernel
#define ROWS_PER_BLK 4                // rows per block in main kernel (64 thr/row)
#define NBLK_B (NB * H / ROWS_PER_BLK)   // 2048

__device__ __half2 g_vsum[NB * H * (W / 2)];   // vertical box sums, fp16 (8 MB)
__device__ float4 g_part4[NBLK_B];             // per-block partials
__device__ unsigned int g_count;               // zero-init; self-resetting

// ================= Kernel A: vertical sliding box sum (fp16 out) =================
__global__ void vert_kernel(const float* __restrict__ mask) {
    const int segs = H / RPB;        // 32
    const int b  = blockIdx.x / segs;
    const int r0 = (blockIdx.x % segs) * RPB;
    const int t  = threadIdx.x;      // 0..255, owns cols 2t, 2t+1

    const float2* mb2 = (const float2*)(mask + (size_t)b * H * W);
    __half2* vb = g_vsum + (size_t)b * H * (W / 2);

    // 4-way tree init of window [r0-15, r0+15]
    float ax[4] = {0.f, 0.f, 0.f, 0.f};
    float ay[4] = {0.f, 0.f, 0.f, 0.f};
    int lo = r0 - KR; if (lo < 0) lo = 0;
    int hi = r0 + KR; if (hi > H - 1) hi = H - 1;
    int k = 0;
    #pragma unroll 4
    for (int j = lo; j <= hi; ++j, ++k) {
        float2 v = __ldcg(&mb2[j * (W / 2) + t]);
        ax[k & 3] += v.x; ay[k & 3] += v.y;
    }
    const float ix = (ax[0] + ax[1]) + (ax[2] + ax[3]);
    const float iy = (ay[0] + ay[1]) + (ay[2] + ay[3]);

    // independent add / sub chains
    float addx = 0.f, addy = 0.f, subx = 0.f, suby = 0.f;
    #pragma unroll
    for (int rr = 0; rr < RPB; ++rr) {
        const int r = r0 + rr;
        __stcg(&vb[r * (W / 2) + t],
               __floats2half2_rn((ix + addx) - subx, (iy + addy) - suby));
        int ar = r + KR + 1;
        int sr = r - KR;
        if (ar < H) {
            float2 v = __ldcg(&mb2[ar * (W / 2) + t]);
            addx += v.x; addy += v.y;
        }
        if (sr >= 0) {
            float2 v = __ldcg(&mb2[sr * (W / 2) + t]);
            subx += v.x; suby += v.y;
        }
    }
}

// ========== Kernel B: shuffle-free horizontal box + elementwise + reduce ==========
// 256 threads, 4 rows per block, 64 threads per row, 8 cols per thread.
// Each thread loads its own halo from the fp16 vsum row: 5 aligned uint4
// (= columns c0-16 .. c0+23, OOB -> 0) and builds a local prefix. No scan,
// no hot-path shuffles, no __syncthreads until the final reduction.
__global__ void __launch_bounds__(256, 6)
main_kernel(const float* __restrict__ pred,
            const float* __restrict__ mask,
            float* __restrict__ out) {
    __shared__ float red[32];        // 8 warps x 4 accumulators
    __shared__ float flag;

    const int t    = threadIdx.x;
    const int wid  = t >> 5;
    const int lane = t & 31;
    const int g    = t >> 6;         // row within block 0..3
    const int u    = t & 63;         // thread within row
    const int c0   = u * 8;

    const int rowg = blockIdx.x * ROWS_PER_BLK + g;   // global row 0..8191
    const int b = rowg >> 9;
    const int r = rowg & (H - 1);

    // ---- vsum halo loads: uint4 idx u-2 .. u+2 (8 halves each) ----
    const uint4* vrow = (const uint4*)(g_vsum + ((size_t)b * H + r) * (W / 2));
    const uint4 zero4 = make_uint4(0u, 0u, 0u, 0u);
    uint4 raw[5];
    #pragma unroll
    for (int k = 0; k < 5; ++k) {
        int idx = u - 2 + k;
        raw[k] = (idx >= 0 && idx < 64) ? vrow[idx] : zero4;
    }

    // ---- streaming elementwise inputs ----
    const size_t rowOff = ((size_t)b * H + r) * W;
    const float4* mrow = (const float4*)(mask + rowOff);
    const size_t predOff = (((size_t)b * 2 + 1) * H + r) * W;
    const float4* prow = (const float4*)(pred + predOff);
    float4 m4[2], p4[2];
    m4[0] = __ldcg(&mrow[u * 2 + 0]);
    m4[1] = __ldcg(&mrow[u * 2 + 1]);
    p4[0] = __ldcg(&prow[u * 2 + 0]);
    p4[1] = __ldcg(&prow[u * 2 + 1]);

    // ---- unpack q[0..39] (= v[c0-16+j]) with two independent prefix chains ----
    // need S[0..7] (lo) and S[31..38] (hi); win_i = S[31+i] - S[i]
    float loS[8], hiS[8];
    float sa = 0.f;                  // chain over j = 0..19
    float sb = 0.f;                  // chain over j = 20..39
    #pragma unroll
    for (int k = 0; k < 5; ++k) {
        const __half2* h2 = (const __half2*)&raw[k];
        #pragma unroll
        for (int l = 0; l < 4; ++l) {
            float2 f = __half22float2(h2[l]);
            const int j0 = k * 8 + l * 2;
            const int j1 = j0 + 1;
            if (j0 < 20) { sa += f.x; if (j0 < 8) loS[j0] = sa; }
            else         { sb += f.x; if (j0 >= 31 && j0 <= 38) hiS[j0 - 31] = sb; }
            if (j1 < 20) { sa += f.y; if (j1 < 8) loS[j1] = sa; }
            else         { sb += f.y; if (j1 >= 31 && j1 <= 38) hiS[j1 - 31] = sb; }
        }
    }
    float win[8];
    #pragma unroll
    for (int i = 0; i < 8; ++i) win[i] = (sa + hiS[i]) - loS[i];

    // ---- fused elementwise + accumulate ----
    float mv[8] = {m4[0].x, m4[0].y, m4[0].z, m4[0].w,
                   m4[1].x, m4[1].y, m4[1].z, m4[1].w};
    float pv[8] = {p4[0].x, p4[0].y, p4[0].z, p4[0].w,
                   p4[1].x, p4[1].y, p4[1].z, p4[1].w};

    float a0 = 0.f, a1 = 0.f, a2 = 0.f, a3 = 0.f;
    #pragma unroll
    for (int i = 0; i < 8; ++i) {
        float box  = win[i] * KKINV;
        float m    = mv[i];
        float p    = pv[i];
        float weit = 1.0f + MUF * fabsf(box - m);

        float eexp = __expf(-fabsf(p));                            // MUFU.EX2
        float bce  = fmaxf(p, 0.0f) - p * m + __logf(1.0f + eexp); // MUFU.LG2
        float rcp  = __fdividef(1.0f, 1.0f + eexp);                // MUFU.RCP
        float ps   = (p >= 0.0f) ? rcp : eexp * rcp;               // sigmoid(p)

        a0 += weit * bce;
        a1 += weit;
        a2 += ps * m * weit;
        a3 += (ps + m) * weit;
    }

    // ---- warp reduction ----
    #pragma unroll
    for (int d = 16; d > 0; d >>= 1) {
        a0 += __shfl_down_sync(0xffffffffu, a0, d);
        a1 += __shfl_down_sync(0xffffffffu, a1, d);
        a2 += __shfl_down_sync(0xffffffffu, a2, d);
        a3 += __shfl_down_sync(0xffffffffu, a3, d);
    }
    if (lane == 0) {
        red[wid * 4 + 0] = a0;
        red[wid * 4 + 1] = a1;
        red[wid * 4 + 2] = a2;
        red[wid * 4 + 3] = a3;
    }
    __syncthreads();

    // ---- cross-warp reduction in warp 0 (shuffle tree) ----
    if (wid == 0) {
        float y = red[lane];                 // lane = w*4 + k, w<8, k<4
        y += __shfl_xor_sync(0xffffffffu, y, 4);
        y += __shfl_xor_sync(0xffffffffu, y, 8);
        y += __shfl_xor_sync(0xffffffffu, y, 16);
        float s0 = __shfl_sync(0xffffffffu, y, 0);
        float s1 = __shfl_sync(0xffffffffu, y, 1);
        float s2 = __shfl_sync(0xffffffffu, y, 2);
        float s3 = __shfl_sync(0xffffffffu, y, 3);
        if (lane == 0) {
            __stcg(&g_part4[blockIdx.x], make_float4(s0, s1, s2, s3));
            unsigned int old;
            asm volatile("atom.acq_rel.gpu.global.add.u32 %0, [%1], %2;"
                         : "=r"(old) : "l"(&g_count), "r"(1u) : "memory");
            flag = (old == NBLK_B - 1) ? 1.f : 0.f;
        }
    }
    __syncthreads();

    // ---------- last block finalizes ----------
    if (flag != 0.f) {
        if (t < 128) {
            const int bb = t >> 3;           // batch 0..15
            const int j  = t & 7;            // chunk 0..7
            float s0 = 0.f, s1 = 0.f, s2 = 0.f, s3 = 0.f;
            const float4* gp = g_part4 + bb * (NBLK_B / NB) + j * 16;
            #pragma unroll
            for (int kk = 0; kk < 16; ++kk) {
                float4 vv = __ldcg(&gp[kk]);
                s0 += vv.x; s1 += vv.y; s2 += vv.z; s3 += vv.w;
            }
            #pragma unroll
            for (int d = 4; d > 0; d >>= 1) {
                s0 += __shfl_down_sync(0xffffffffu, s0, d, 8);
                s1 += __shfl_down_sync(0xffffffffu, s1, d, 8);
                s2 += __shfl_down_sync(0xffffffffu, s2, d, 8);
                s3 += __shfl_down_sync(0xffffffffu, s3, d, 8);
            }
            if (j == 0) {
                float wbce = s0 / s1;
                float wiou = 1.0f - (s2 + 1.0f) / (s3 - s2 + 1.0f);
                red[bb] = wbce + wiou;
            }
        }
        __syncthreads();
        if (t == 0) {
            float s = 0.f;
            #pragma unroll
            for (int kk = 0; kk < NB; ++kk) s += red[kk];
            out[0] = s * (1.0f / NB);
            g_count = 0;                     // self-reset for next graph replay
        }
    }
}

extern "C" void kernel_launch(void* const* d_in, const int* in_sizes, int n_in,
                              void* d_out, int out_size) {
    const float* pred = (const float*)d_in[0];
    const float* mask = (const float*)d_in[1];
    if (n_in >= 2 && in_sizes[0] == NB * H * W && in_sizes[1] == NB * 2 * H * W) {
        mask = (const float*)d_in[0];
        pred = (const float*)d_in[1];
    }
    float* out = (float*)d_out;

    vert_kernel<<<NB * (H / RPB), 256>>>(mask);
    main_kernel<<<NBLK_B, 256>>>(pred, mask, out);
}

// round 9
// speedup vs baseline: 1.0013x; 1.0013x over previous
#include <cuda_runtime.h>
#include <math.h>

#define NB 16
#define H 512
#define W 512
#define KR 15
#define MUF 5.0f
#define QS 8.0f                       // vsum quant scale
#define BOXSCALE (1.0f/(961.0f*8.0f)) // KKINV / QS
#define RPB 16                        // rows per block in vert kernel
#define ROWS_PER_BLK 4                // rows per block in main kernel
#define VSTRIDE 544                   // 16B pad | 512 cols | 16B pad
#define NBLK_B (NB * H / ROWS_PER_BLK)   // 2048

// zero-initialized; pad bytes are never written so they stay 0 forever
__device__ unsigned char g_vu8[NB * H * VSTRIDE];   // ~4.45 MB
__device__ float4 g_part4[NBLK_B];                  // per-block partials
__device__ unsigned int g_count;                    // zero-init; self-resetting

// ================= Kernel A: vertical sliding box sum (u8 out) =================
__global__ void vert_kernel(const float* __restrict__ mask) {
    const int segs = H / RPB;        // 32
    const int b  = blockIdx.x / segs;
    const int r0 = (blockIdx.x % segs) * RPB;
    const int t  = threadIdx.x;      // 0..255, owns cols 2t, 2t+1

    const float2* mb2 = (const float2*)(mask + (size_t)b * H * W);
    unsigned short* vb = (unsigned short*)(g_vu8 + (size_t)b * H * VSTRIDE);

    // 4-way tree init of window [r0-15, r0+15]
    float ax[4] = {0.f, 0.f, 0.f, 0.f};
    float ay[4] = {0.f, 0.f, 0.f, 0.f};
    int lo = r0 - KR; if (lo < 0) lo = 0;
    int hi = r0 + KR; if (hi > H - 1) hi = H - 1;
    int k = 0;
    #pragma unroll 4
    for (int j = lo; j <= hi; ++j, ++k) {
        float2 v = __ldcg(&mb2[j * (W / 2) + t]);
        ax[k & 3] += v.x; ay[k & 3] += v.y;
    }
    const float ix = (ax[0] + ax[1]) + (ax[2] + ax[3]);
    const float iy = (ay[0] + ay[1]) + (ay[2] + ay[3]);

    // independent add / sub chains
    float addx = 0.f, addy = 0.f, subx = 0.f, suby = 0.f;
    #pragma unroll
    for (int rr = 0; rr < RPB; ++rr) {
        const int r = r0 + rr;
        float vx = (ix + addx) - subx;
        float vy = (iy + addy) - suby;
        unsigned qx = (unsigned)__float2int_rn(vx * QS);
        unsigned qy = (unsigned)__float2int_rn(vy * QS);
        __stcg(&vb[r * (VSTRIDE / 2) + 8 + t], (unsigned short)(qx | (qy << 8)));
        int ar = r + KR + 1;
        int sr = r - KR;
        if (ar < H) {
            float2 v = __ldcg(&mb2[ar * (W / 2) + t]);
            addx += v.x; addy += v.y;
        }
        if (sr >= 0) {
            float2 v = __ldcg(&mb2[sr * (W / 2) + t]);
            subx += v.x; suby += v.y;
        }
    }
}

// ========== Kernel B: dp4a horizontal box + elementwise + reduce ==========
// 256 threads, 4 rows per block, 64 threads per row, 8 cols per thread.
// vsum row is u8 with 16-byte zero pads: thread u loads bytes 8u..8u+39
// (5 aligned LDG.64, no predicates) and computes the 31-tap window through
// dp4a integer prefix sums. No cvts, no shuffles, no barriers in hot path.
__global__ void __launch_bounds__(256, 6)
main_kernel(const float* __restrict__ pred,
            const float* __restrict__ mask,
            float* __restrict__ out) {
    __shared__ float red[32];        // 8 warps x 4 accumulators
    __shared__ float flag;

    const int t    = threadIdx.x;
    const int wid  = t >> 5;
    const int lane = t & 31;
    const int g    = t >> 6;         // row within block 0..3
    const int u    = t & 63;         // thread within row

    const int rowg = blockIdx.x * ROWS_PER_BLK + g;   // global row 0..8191
    const int b = rowg >> 9;
    const int r = rowg & (H - 1);

    // ---- vsum halo loads: bytes 8u .. 8u+39 as 5 aligned uint2 ----
    const uint2* vrow = (const uint2*)(g_vu8 + ((size_t)b * H + r) * VSTRIDE);
    uint2 L0 = vrow[u + 0];
    uint2 L1 = vrow[u + 1];
    uint2 L2 = vrow[u + 2];
    uint2 L3 = vrow[u + 3];
    uint2 L4 = vrow[u + 4];

    // ---- streaming elementwise inputs ----
    const size_t rowOff = ((size_t)b * H + r) * W;
    const float4* mrow = (const float4*)(mask + rowOff);
    const size_t predOff = (((size_t)b * 2 + 1) * H + r) * W;
    const float4* prow = (const float4*)(pred + predOff);
    float4 m4[2], p4[2];
    m4[0] = __ldcg(&mrow[u * 2 + 0]);
    m4[1] = __ldcg(&mrow[u * 2 + 1]);
    p4[0] = __ldcg(&prow[u * 2 + 0]);
    p4[1] = __ldcg(&prow[u * 2 + 1]);

    // ---- integer prefix over 40 bytes via dp4a ----
    unsigned w0 = L0.x, w1 = L0.y, w2 = L1.x, w3 = L1.y, w4 = L2.x,
             w5 = L2.y, w6 = L3.x, w7 = L3.y, w8 = L4.x, w9 = L4.y;
    const unsigned M1 = 0x01010101u;
    unsigned wp1 = __dp4a(w0, M1, 0u);
    unsigned wp2 = __dp4a(w1, M1, wp1);
    unsigned wp3 = __dp4a(w2, M1, wp2);
    unsigned wp4 = __dp4a(w3, M1, wp3);
    unsigned wp5 = __dp4a(w4, M1, wp4);
    unsigned wp6 = __dp4a(w5, M1, wp5);
    unsigned wp7 = __dp4a(w6, M1, wp6);
    unsigned wp8 = __dp4a(w7, M1, wp7);
    unsigned wp9 = __dp4a(w8, M1, wp8);

    // S_inc[k] = sum of bytes 0..k ; need k = 0..7 and k = 31..38
    unsigned loS[8], hiS[8];
    loS[0] = __dp4a(w0, 0x00000001u, 0u);
    loS[1] = __dp4a(w0, 0x00000101u, 0u);
    loS[2] = __dp4a(w0, 0x00010101u, 0u);
    loS[3] = wp1;
    loS[4] = __dp4a(w1, 0x00000001u, wp1);
    loS[5] = __dp4a(w1, 0x00000101u, wp1);
    loS[6] = __dp4a(w1, 0x00010101u, wp1);
    loS[7] = wp2;
    hiS[0] = wp8;                                    // k=31
    hiS[1] = __dp4a(w8, 0x00000001u, wp8);           // k=32
    hiS[2] = __dp4a(w8, 0x00000101u, wp8);
    hiS[3] = __dp4a(w8, 0x00010101u, wp8);
    hiS[4] = wp9;                                    // k=35
    hiS[5] = __dp4a(w9, 0x00000001u, wp9);
    hiS[6] = __dp4a(w9, 0x00000101u, wp9);
    hiS[7] = __dp4a(w9, 0x00010101u, wp9);

    // ---- fused elementwise + accumulate ----
    float mv[8] = {m4[0].x, m4[0].y, m4[0].z, m4[0].w,
                   m4[1].x, m4[1].y, m4[1].z, m4[1].w};
    float pv[8] = {p4[0].x, p4[0].y, p4[0].z, p4[0].w,
                   p4[1].x, p4[1].y, p4[1].z, p4[1].w};

    float a0 = 0.f, a1 = 0.f, a2 = 0.f, a3 = 0.f;
    #pragma unroll
    for (int i = 0; i < 8; ++i) {
        float box  = (float)(int)(hiS[i] - loS[i]) * BOXSCALE;
        float m    = mv[i];
        float p    = pv[i];
        float weit = 1.0f + MUF * fabsf(box - m);

        float eexp = __expf(-fabsf(p));                            // MUFU.EX2
        float bce  = fmaxf(p, 0.0f) - p * m + __logf(1.0f + eexp); // MUFU.LG2
        float rcp  = __fdividef(1.0f, 1.0f + eexp);                // MUFU.RCP
        float ps   = (p >= 0.0f) ? rcp : eexp * rcp;               // sigmoid(p)

        a0 += weit * bce;
        a1 += weit;
        float wps = weit * ps;
        a2 += wps * m;
        a3 += wps + weit * m;
    }

    // ---- warp reduction ----
    #pragma unroll
    for (int d = 16; d > 0; d >>= 1) {
        a0 += __shfl_down_sync(0xffffffffu, a0, d);
        a1 += __shfl_down_sync(0xffffffffu, a1, d);
        a2 += __shfl_down_sync(0xffffffffu, a2, d);
        a3 += __shfl_down_sync(0xffffffffu, a3, d);
    }
    if (lane == 0) {
        red[wid * 4 + 0] = a0;
        red[wid * 4 + 1] = a1;
        red[wid * 4 + 2] = a2;
        red[wid * 4 + 3] = a3;
    }
    __syncthreads();

    // ---- cross-warp reduction in warp 0 (shuffle tree) ----
    if (wid == 0) {
        float y = red[lane];                 // lane = w*4 + k, w<8, k<4
        y += __shfl_xor_sync(0xffffffffu, y, 4);
        y += __shfl_xor_sync(0xffffffffu, y, 8);
        y += __shfl_xor_sync(0xffffffffu, y, 16);
        float s0 = __shfl_sync(0xffffffffu, y, 0);
        float s1 = __shfl_sync(0xffffffffu, y, 1);
        float s2 = __shfl_sync(0xffffffffu, y, 2);
        float s3 = __shfl_sync(0xffffffffu, y, 3);
        if (lane == 0) {
            __stcg(&g_part4[blockIdx.x], make_float4(s0, s1, s2, s3));
            unsigned int old;
            asm volatile("atom.acq_rel.gpu.global.add.u32 %0, [%1], %2;"
                         : "=r"(old) : "l"(&g_count), "r"(1u) : "memory");
            flag = (old == NBLK_B - 1) ? 1.f : 0.f;
        }
    }
    __syncthreads();

    // ---------- last block finalizes ----------
    if (flag != 0.f) {
        if (t < 128) {
            const int bb = t >> 3;           // batch 0..15
            const int j  = t & 7;            // chunk 0..7
            float s0 = 0.f, s1 = 0.f, s2 = 0.f, s3 = 0.f;
            const float4* gp = g_part4 + bb * (NBLK_B / NB) + j * 16;
            #pragma unroll
            for (int kk = 0; kk < 16; ++kk) {
                float4 vv = __ldcg(&gp[kk]);
                s0 += vv.x; s1 += vv.y; s2 += vv.z; s3 += vv.w;
            }
            #pragma unroll
            for (int d = 4; d > 0; d >>= 1) {
                s0 += __shfl_down_sync(0xffffffffu, s0, d, 8);
                s1 += __shfl_down_sync(0xffffffffu, s1, d, 8);
                s2 += __shfl_down_sync(0xffffffffu, s2, d, 8);
                s3 += __shfl_down_sync(0xffffffffu, s3, d, 8);
            }
            if (j == 0) {
                float wbce = s0 / s1;
                float wiou = 1.0f - (s2 + 1.0f) / (s3 - s2 + 1.0f);
                red[bb] = wbce + wiou;
            }
        }
        __syncthreads();
        if (t == 0) {
            float s = 0.f;
            #pragma unroll
            for (int kk = 0; kk < NB; ++kk) s += red[kk];
            out[0] = s * (1.0f / NB);
            g_count = 0;                     // self-reset for next graph replay
        }
    }
}

extern "C" void kernel_launch(void* const* d_in, const int* in_sizes, int n_in,
                              void* d_out, int out_size) {
    const float* pred = (const float*)d_in[0];
    const float* mask = (const float*)d_in[1];
    if (n_in >= 2 && in_sizes[0] == NB * H * W && in_sizes[1] == NB * 2 * H * W) {
        mask = (const float*)d_in[0];
        pred = (const float*)d_in[1];
    }
    float* out = (float*)d_out;

    vert_kernel<<<NB * (H / RPB), 256>>>(mask);
    main_kernel<<<NBLK_B, 256>>>(pred, mask, out);
}